// round 10
// baseline (speedup 1.0000x reference)
#include <cuda_runtime.h>
#include <cstdint>
#include <cstddef>

// DWTModelFullBand: reference = idwt2(idwt2(dwt2(dwt2(x)))) == identity
// (verified R2, rel_err 6.2e-8). Required work = D2D copy of 96 MiB.
//
// R9: split the copy across TWO copy engines. Two memcpy nodes on forked
// streams capture as parallel graph nodes -> two CEs run halves
// concurrently. If a single CE (not DRAM) was the R8 limiter, this moves
// device time toward the 192MB/8TB/s ~ 24us floor.
//
// Streams/events are created once on the first call (the correctness run,
// outside capture) and reused for the capture call. No cudaMalloc-family
// API is ever invoked.

static cudaStream_t g_s1 = nullptr;
static cudaEvent_t  g_fork = nullptr, g_join = nullptr;

extern "C" void kernel_launch(void* const* d_in, const int* in_sizes, int n_in,
                              void* d_out, int out_size) {
    if (g_s1 == nullptr) {
        cudaStreamCreateWithFlags(&g_s1, cudaStreamNonBlocking);
        cudaEventCreateWithFlags(&g_fork, cudaEventDisableTiming);
        cudaEventCreateWithFlags(&g_join, cudaEventDisableTiming);
    }

    size_t bytes = (size_t)in_sizes[0] * sizeof(float);  // 96 MiB
    size_t half  = bytes / 2;
    const char* src = (const char*)d_in[0];
    char*       dst = (char*)d_out;

    // Fork: side stream joins the capture (legacy) stream.
    cudaEventRecord(g_fork, 0);
    cudaStreamWaitEvent(g_s1, g_fork, 0);

    // Parallel halves on two streams -> two memcpy nodes -> two CEs.
    cudaMemcpyAsync(dst,        src,        half,         cudaMemcpyDeviceToDevice, 0);
    cudaMemcpyAsync(dst + half, src + half, bytes - half, cudaMemcpyDeviceToDevice, g_s1);

    // Join back into the capture stream.
    cudaEventRecord(g_join, g_s1);
    cudaStreamWaitEvent(0, g_join, 0);
}

// round 11
// speedup vs baseline: 1.0721x; 1.0721x over previous
#include <cuda_runtime.h>
#include <cstdint>

// DWTModelFullBand: reference = idwt2(idwt2(dwt2(dwt2(x)))) == identity
// (exact algebraic inverse, verified R2: rel_err 6.2e-8). Required work
// reduces to a D2D copy of 96 MiB.
//
// FINAL (R8 revert): single copy-engine memcpy node.
// Measured design space:
//   - SM f8 copy kernel:        27.2us device, dur 36.8
//   - L2 evict_last pinning:    refuted (no carveout -> hints inert, R5)
//   - burst batching/tail-free: neutral (DRAM-bound, R6)
//   - single CE memcpy node:    ~25.7us device (~94% of HBM spec), dur 35.3  <= best
//   - dual-CE fork/join:        regression (+2.8us event-node overhead,
//                               no device gain: DRAM-bound, not CE-bound, R9)
// Remaining gap to dur is fixed graph-replay overhead (~9.6us), harness-side.

extern "C" void kernel_launch(void* const* d_in, const int* in_sizes, int n_in,
                              void* d_out, int out_size) {
    size_t bytes = (size_t)in_sizes[0] * sizeof(float);  // 96 MiB
    cudaMemcpyAsync(d_out, d_in[0], bytes, cudaMemcpyDeviceToDevice, 0);
}